// round 1
// baseline (speedup 1.0000x reference)
#include <cuda_runtime.h>
#include <math.h>

#define BATCH 8
#define CIN 256
#define HH 100
#define WW 152
#define HW 15200
#define NC 81
#define NKEEP 100
#define NOUT1 (BATCH*CIN*NKEEP)   /* 204800 */

// Scratch (device globals: allocation-free per harness rules)
__device__ float g_hid[(size_t)BATCH*CIN*HW];     // conv1 output (relu'd)
__device__ float g_w1t[CIN*9*CIN];                // w1 transposed to [ci][k][co]
__device__ int   g_cls[BATCH*HW];
__device__ float g_pv[BATCH*HW];
__device__ unsigned long long g_keys[BATCH*HW];
__device__ int   g_topk[BATCH*NKEEP];

// ---------------------------------------------------------------------------
// w1 (co,ci,kh,kw) -> g_w1t[ci][k][co] for coalesced smem staging in conv3x3
// ---------------------------------------------------------------------------
__global__ void k_transpose_w1(const float* __restrict__ w1){
  int i = blockIdx.x*256 + threadIdx.x;
  if (i < CIN*CIN*9){
    int k = i % 9; int ci = (i/9) % CIN; int co = i/(9*CIN);
    g_w1t[ci*9*CIN + k*CIN + co] = w1[i];
  }
}

// ---------------------------------------------------------------------------
// 3x3 SAME conv, 256->256, + bias + relu.
// Tile: 8x16 spatial x 64 co per block, ci in chunks of 16.
// Thread: 4 co x 8 contiguous px (one row), 288 FFMA per ci.
// ---------------------------------------------------------------------------
__global__ __launch_bounds__(256,2) void k_conv3x3(const float* __restrict__ x,
                                                   const float* __restrict__ b1){
  __shared__ float s_in[16][10][18];   // [ci][h+2][w+2]
  __shared__ float s_w[16][9][64];     // [ci][k][co]
  int tid = threadIdx.x;
  int x0 = blockIdx.x*16, y0 = blockIdx.y*8;
  int bz = blockIdx.z;
  int b   = bz >> 2;
  int co0 = (bz & 3) * 64;
  int g    = tid & 15;       // pixel group
  int cog  = tid >> 4;       // co group (4 co each)
  int prow = g >> 1;         // 0..7
  int pcol = (g & 1) * 8;    // 0 or 8
  int co = co0 + cog*4;

  float acc[4][8];
  #pragma unroll
  for (int i=0;i<4;i++){
    float bv = b1[co+i];
    #pragma unroll
    for (int j=0;j<8;j++) acc[i][j]=bv;
  }

  const float* xb = x + (size_t)b*CIN*HW;

  for (int ci0=0; ci0<CIN; ci0+=16){
    __syncthreads();
    // stage input 16ci x 10 x 18 (zero-padded halo)
    #pragma unroll 1
    for (int i=tid; i<16*10*18; i+=256){
      int lx = i % 18; int t = i/18; int ly = t % 10; int lci = t/10;
      int gx = x0 - 1 + lx, gy = y0 - 1 + ly;
      float v = 0.f;
      if ((unsigned)gx < WW && (unsigned)gy < HH)
        v = xb[(size_t)(ci0+lci)*HW + gy*WW + gx];
      s_in[lci][ly][lx] = v;
    }
    // stage weights 16ci x 9 x 64co (coalesced: co fastest in g_w1t)
    #pragma unroll 1
    for (int i=tid; i<16*9*64; i+=256){
      int lco = i & 63; int t = i >> 6; int k = t % 9; int lci = t/9;
      s_w[lci][k][lco] = g_w1t[(ci0+lci)*9*CIN + k*CIN + co0 + lco];
    }
    __syncthreads();

    #pragma unroll 1
    for (int ci=0; ci<16; ci++){
      float wr[9][4];
      #pragma unroll
      for (int k=0;k<9;k++){
        float4 wv = *(const float4*)&s_w[ci][k][cog*4];
        wr[k][0]=wv.x; wr[k][1]=wv.y; wr[k][2]=wv.z; wr[k][3]=wv.w;
      }
      #pragma unroll
      for (int ky=0;ky<3;ky++){
        float r[10];
        #pragma unroll
        for (int u=0;u<10;u++) r[u] = s_in[ci][prow+ky][pcol+u];
        #pragma unroll
        for (int kx=0;kx<3;kx++){
          #pragma unroll
          for (int i=0;i<4;i++){
            float wv = wr[ky*3+kx][i];
            #pragma unroll
            for (int j=0;j<8;j++) acc[i][j] = fmaf(r[kx+j], wv, acc[i][j]);
          }
        }
      }
    }
  }

  int gy = y0 + prow, gxb = x0 + pcol;
  if (gy < HH && gxb < WW){
    #pragma unroll
    for (int i=0;i<4;i++){
      float* hp = g_hid + ((size_t)b*CIN + (co+i))*HW + gy*WW + gxb;
      float4 v0, v1;
      v0.x=fmaxf(acc[i][0],0.f); v0.y=fmaxf(acc[i][1],0.f);
      v0.z=fmaxf(acc[i][2],0.f); v0.w=fmaxf(acc[i][3],0.f);
      v1.x=fmaxf(acc[i][4],0.f); v1.y=fmaxf(acc[i][5],0.f);
      v1.z=fmaxf(acc[i][6],0.f); v1.w=fmaxf(acc[i][7],0.f);
      *(float4*)hp = v0; *(float4*)(hp+4) = v1;
    }
  }
}

// ---------------------------------------------------------------------------
// 1x1 conv 256->81 + bias. One px per thread, co in 3 chunks of 27 (28 padded).
// ---------------------------------------------------------------------------
__global__ __launch_bounds__(256) void k_conv1x1(const float* __restrict__ w2,
                                                 const float* __restrict__ b2,
                                                 float* __restrict__ logits){
  __shared__ float s_w[256*28];    // [ci][j] padded, 28KB
  int tid = threadIdx.x;
  int b  = blockIdx.y;
  int px = blockIdx.x*256 + tid;
  const float* hb = g_hid + (size_t)b*CIN*HW;
  float* ob = logits + (size_t)b*NC*HW;

  for (int cc=0; cc<3; cc++){
    __syncthreads();
    for (int i=tid; i<256*28; i+=256){
      int j = i % 28; int ci = i/28;
      s_w[i] = (j<27) ? w2[(cc*27+j)*CIN + ci] : 0.f;
    }
    __syncthreads();
    if (px < HW){
      float acc[28];
      #pragma unroll
      for (int j=0;j<28;j++) acc[j] = (j<27) ? b2[cc*27+j] : 0.f;
      #pragma unroll 4
      for (int ci=0; ci<CIN; ci++){
        float v = hb[(size_t)ci*HW + px];
        const float4* wp = (const float4*)(s_w + ci*28);
        #pragma unroll
        for (int q=0;q<7;q++){
          float4 w4 = wp[q];
          acc[q*4+0] = fmaf(v, w4.x, acc[q*4+0]);
          acc[q*4+1] = fmaf(v, w4.y, acc[q*4+1]);
          acc[q*4+2] = fmaf(v, w4.z, acc[q*4+2]);
          acc[q*4+3] = fmaf(v, w4.w, acc[q*4+3]);
        }
      }
      #pragma unroll
      for (int j=0;j<27;j++) ob[(size_t)(cc*27+j)*HW + px] = acc[j];
    }
  }
}

// ---------------------------------------------------------------------------
// Per-pixel: softmax over 81 channels, argmax over first 80 (first-max wins),
// p = prob at argmax channel. (After masking only that channel is nonzero.)
// ---------------------------------------------------------------------------
__global__ void k_softmax(const float* __restrict__ logits){
  int i = blockIdx.x*256 + threadIdx.x;
  if (i >= BATCH*HW) return;
  int b = i / HW, px = i - b*HW;
  const float* lp = logits + (size_t)b*NC*HW + px;
  float M = -1e30f, best = -1e30f; int bi = 0;
  #pragma unroll 1
  for (int c=0;c<NC;c++){
    float v = lp[(size_t)c*HW];
    if (c < 80 && v > best){ best = v; bi = c; }
    M = fmaxf(M, v);
  }
  float s = 0.f;
  #pragma unroll 1
  for (int c=0;c<NC;c++) s += expf(lp[(size_t)c*HW] - M);
  g_pv[i] = expf(best - M) / s;
  g_cls[i] = bi;
}

// ---------------------------------------------------------------------------
// score = p + 1 if (p>=eps and no in-bounds 8-neighbor with same class and
// strictly larger p). Emits sortable key: (score_bits<<32) | (~px) so ties
// prefer the smaller index (lax.top_k semantics). score >= 0 always.
// ---------------------------------------------------------------------------
__global__ void k_score(){
  int i = blockIdx.x*256 + threadIdx.x;
  if (i >= BATCH*HW) return;
  int b = i / HW, px = i - b*HW;
  int y = px / WW, xx = px - y*WW;
  float p = g_pv[i]; int cls = g_cls[i];
  bool flag = (p >= 1e-6f);
  if (flag){
    #pragma unroll
    for (int dy=-1; dy<=1; dy++){
      #pragma unroll
      for (int dx=-1; dx<=1; dx++){
        if (dy==0 && dx==0) continue;
        int ny = y+dy, nx = xx+dx;
        if ((unsigned)ny < HH && (unsigned)nx < WW){
          int j = b*HW + ny*WW + nx;
          if (g_cls[j]==cls && g_pv[j] > p) flag = false;
        }
      }
    }
  }
  float score = p + (flag ? 1.f : 0.f);
  g_keys[i] = (((unsigned long long)__float_as_uint(score))<<32)
              | (unsigned long long)(0xFFFFFFFFu - (unsigned)px);
}

// ---------------------------------------------------------------------------
// Top-100 per batch: 100 iterations of block-wide argmax over 15200 keys
// (L2-resident), zero the winner each round. Exact lax.top_k ordering.
// ---------------------------------------------------------------------------
__global__ void k_topk(){
  __shared__ unsigned long long s_red[256];
  int b = blockIdx.x, tid = threadIdx.x;
  unsigned long long* kb = g_keys + (size_t)b*HW;
  for (int it=0; it<NKEEP; it++){
    unsigned long long best = 0ull;
    for (int i=tid; i<HW; i+=256){
      unsigned long long k = kb[i];
      if (k > best) best = k;
    }
    s_red[tid] = best;
    __syncthreads();
    #pragma unroll
    for (int s=128; s>0; s>>=1){
      if (tid < s && s_red[tid+s] > s_red[tid]) s_red[tid] = s_red[tid+s];
      __syncthreads();
    }
    unsigned long long win = s_red[0];
    int wpx = (int)(0xFFFFFFFFu - (unsigned)(win & 0xFFFFFFFFull));
    if (tid==0){
      g_topk[b*NKEEP+it] = wpx;
      kb[wpx] = 0ull;      // exclude winner; __syncthreads gives block visibility
    }
    __syncthreads();
  }
}

// ---------------------------------------------------------------------------
// Gather x and pos at top-k indices. out layout: [proposals | pos | logits]
// ---------------------------------------------------------------------------
__global__ void k_gather(const float* __restrict__ x, const float* __restrict__ pos,
                         float* __restrict__ out){
  int i = blockIdx.x*256 + threadIdx.x;
  if (i >= NOUT1) return;
  int k = i % NKEEP; int t = i / NKEEP; int c = t % CIN; int b = t / CIN;
  int px = g_topk[b*NKEEP + k];
  out[i]         = x[((size_t)b*CIN + c)*HW + px];
  out[NOUT1 + i] = pos[(size_t)c*HW + px];
}

// ---------------------------------------------------------------------------
extern "C" void kernel_launch(void* const* d_in, const int* in_sizes, int n_in,
                              void* d_out, int out_size){
  (void)in_sizes; (void)n_in; (void)out_size;
  const float* x   = (const float*)d_in[0];
  const float* pos = (const float*)d_in[1];
  const float* w1  = (const float*)d_in[2];
  const float* b1  = (const float*)d_in[3];
  const float* w2  = (const float*)d_in[4];
  const float* b2  = (const float*)d_in[5];
  float* out = (float*)d_out;
  float* logits = out + 2*NOUT1;

  k_transpose_w1<<<(CIN*CIN*9+255)/256, 256>>>(w1);
  k_conv3x3<<<dim3(10,13,BATCH*4), 256>>>(x, b1);
  k_conv1x1<<<dim3((HW+255)/256, BATCH), 256>>>(w2, b2, logits);
  k_softmax<<<(BATCH*HW+255)/256, 256>>>(logits);
  k_score<<<(BATCH*HW+255)/256, 256>>>();
  k_topk<<<BATCH, 256>>>();
  k_gather<<<(NOUT1+255)/256, 256>>>(x, pos, out);
}

// round 2
// speedup vs baseline: 1.1804x; 1.1804x over previous
#include <cuda_runtime.h>
#include <math.h>

#define BATCH 8
#define CIN 256
#define HH 100
#define WW 152
#define HW 15200
#define NC 81
#define NKEEP 100
#define NOUT1 (BATCH*CIN*NKEEP)   /* 204800 */

// Scratch (device globals: allocation-free per harness rules)
__device__ float g_hid[(size_t)BATCH*CIN*HW];     // conv1 output (relu'd)
__device__ float g_w1t[CIN*9*CIN];                // w1 transposed to [ci][k][co]
__device__ int   g_cls[BATCH*HW];
__device__ float g_pv[BATCH*HW];
__device__ unsigned long long g_keys[BATCH*HW];
__device__ int   g_topk[BATCH*NKEEP];

// Packed f32x2 helpers (SASS FFMA2 — 2x fp32 FMA throughput, exact IEEE fp32)
#define FMA2(d,a,b,c) asm("fma.rn.f32x2 %0, %1, %2, %3;" : "=l"(d) : "l"(a), "l"(b), "l"(c))
#define PACK2(d,lo,hi) asm("mov.b64 %0, {%1, %2};" : "=l"(d) : "f"(lo), "f"(hi))
#define UNPACK2(lo,hi,s) asm("mov.b64 {%0, %1}, %2;" : "=f"(lo), "=f"(hi) : "l"(s))

// ---------------------------------------------------------------------------
// w1 (co,ci,kh,kw) -> g_w1t[ci][k][co] for coalesced smem staging in conv3x3
// ---------------------------------------------------------------------------
__global__ void k_transpose_w1(const float* __restrict__ w1){
  int i = blockIdx.x*256 + threadIdx.x;
  if (i < CIN*CIN*9){
    int k = i % 9; int ci = (i/9) % CIN; int co = i/(9*CIN);
    g_w1t[ci*9*CIN + k*CIN + co] = w1[i];
  }
}

// ---------------------------------------------------------------------------
// 3x3 SAME conv, 256->256, + bias + relu, using packed f32x2 FMA.
// Block tile: 16 rows x 16 cols x 64 co, ci chunks of 8.
// Thread: 4 co x 8 cols x 2 rows (the row pair is the f32x2 lane pair).
// Shared input stored as duplicated vertical pairs so every inner data
// access is one LDS.64, no per-FMA packing.
// ---------------------------------------------------------------------------
__global__ __launch_bounds__(256,2) void k_conv3x3(const float* __restrict__ x,
                                                   const float* __restrict__ b1){
  __shared__ unsigned long long s_v[8][17][19];  // [ci][pair-row p=(y0-1+p, y0+p)][col]
  __shared__ float s_w[8][9][64];                // [ci][k][co]
  int tid = threadIdx.x;
  int x0 = blockIdx.x*16, y0 = blockIdx.y*16;
  int bz = blockIdx.z;
  int b   = bz >> 2;
  int co0 = (bz & 3) * 64;
  int cg = tid & 1;          // col group (0..1): cols cg*8 .. cg*8+7
  int rg = (tid >> 1) & 7;   // row group (0..7): rows rg*2, rg*2+1
  int og = tid >> 4;         // co group (0..15): 4 co each
  int co = co0 + og*4;
  int c0 = cg*8;

  unsigned long long acc[4][8];
  #pragma unroll
  for (int i=0;i<4;i++){
    float bv = b1[co+i];
    unsigned long long bp; PACK2(bp, bv, bv);
    #pragma unroll
    for (int j=0;j<8;j++) acc[i][j] = bp;
  }

  const float* xb = x + (size_t)b*CIN*HW;

  for (int ci0=0; ci0<CIN; ci0+=8){
    __syncthreads();
    // stage input 8ci x 18x18 halo region into vertical-pair layout
    #pragma unroll 1
    for (int i=tid; i<8*18*18; i+=256){
      int xx = i % 18; int t = i/18; int yy = t % 18; int ci = t/18;
      int gx = x0 - 1 + xx, gy = y0 - 1 + yy;
      float v = 0.f;
      if ((unsigned)gx < WW && (unsigned)gy < HH)
        v = xb[(size_t)(ci0+ci)*HW + gy*WW + gx];
      if (yy <= 16) ((float*)&s_v[ci][yy][xx])[0]   = v;  // lo of pair yy
      if (yy >= 1)  ((float*)&s_v[ci][yy-1][xx])[1] = v;  // hi of pair yy-1
    }
    // stage weights 8ci x 9 x 64co (coalesced: co fastest in g_w1t)
    #pragma unroll 1
    for (int i=tid; i<8*9*64; i+=256){
      int lco = i & 63; int t = i >> 6; int k = t % 9; int ci = t/9;
      s_w[ci][k][lco] = g_w1t[(ci0+ci)*9*CIN + k*CIN + co0 + lco];
    }
    __syncthreads();

    #pragma unroll 1
    for (int ci=0; ci<8; ci++){
      #pragma unroll
      for (int ky=0; ky<3; ky++){
        int p = rg*2 + ky;
        unsigned long long v[10];
        #pragma unroll
        for (int u=0;u<10;u++) v[u] = s_v[ci][p][c0+u];
        #pragma unroll
        for (int kx=0;kx<3;kx++){
          float4 w4 = *(const float4*)&s_w[ci][ky*3+kx][og*4];
          unsigned long long wd0, wd1, wd2, wd3;
          PACK2(wd0, w4.x, w4.x); PACK2(wd1, w4.y, w4.y);
          PACK2(wd2, w4.z, w4.z); PACK2(wd3, w4.w, w4.w);
          #pragma unroll
          for (int j=0;j<8;j++){
            FMA2(acc[0][j], v[kx+j], wd0, acc[0][j]);
            FMA2(acc[1][j], v[kx+j], wd1, acc[1][j]);
            FMA2(acc[2][j], v[kx+j], wd2, acc[2][j]);
            FMA2(acc[3][j], v[kx+j], wd3, acc[3][j]);
          }
        }
      }
    }
  }

  // epilogue: unpack, relu, store two rows of 8 per co
  int gy = y0 + rg*2;
  int gx = x0 + c0;
  if (gx + 7 < WW){
    #pragma unroll
    for (int i=0;i<4;i++){
      float lo[8], hi[8];
      #pragma unroll
      for (int j=0;j<8;j++){
        UNPACK2(lo[j], hi[j], acc[i][j]);
        lo[j] = fmaxf(lo[j], 0.f); hi[j] = fmaxf(hi[j], 0.f);
      }
      float* base = g_hid + ((size_t)b*CIN + (co+i))*HW;
      if (gy < HH){
        float* hp = base + (size_t)gy*WW + gx;
        *(float4*)hp     = make_float4(lo[0],lo[1],lo[2],lo[3]);
        *(float4*)(hp+4) = make_float4(lo[4],lo[5],lo[6],lo[7]);
      }
      if (gy+1 < HH){
        float* hp = base + (size_t)(gy+1)*WW + gx;
        *(float4*)hp     = make_float4(hi[0],hi[1],hi[2],hi[3]);
        *(float4*)(hp+4) = make_float4(hi[4],hi[5],hi[6],hi[7]);
      }
    }
  }
}

// ---------------------------------------------------------------------------
// 1x1 conv 256->81 + bias. One px per thread, co in 3 chunks of 27 (28 padded).
// ---------------------------------------------------------------------------
__global__ __launch_bounds__(256) void k_conv1x1(const float* __restrict__ w2,
                                                 const float* __restrict__ b2,
                                                 float* __restrict__ logits){
  __shared__ float s_w[256*28];    // [ci][j] padded, 28KB
  int tid = threadIdx.x;
  int b  = blockIdx.y;
  int px = blockIdx.x*256 + tid;
  const float* hb = g_hid + (size_t)b*CIN*HW;
  float* ob = logits + (size_t)b*NC*HW;

  for (int cc=0; cc<3; cc++){
    __syncthreads();
    for (int i=tid; i<256*28; i+=256){
      int j = i % 28; int ci = i/28;
      s_w[i] = (j<27) ? w2[(cc*27+j)*CIN + ci] : 0.f;
    }
    __syncthreads();
    if (px < HW){
      float acc[28];
      #pragma unroll
      for (int j=0;j<28;j++) acc[j] = (j<27) ? b2[cc*27+j] : 0.f;
      #pragma unroll 4
      for (int ci=0; ci<CIN; ci++){
        float v = hb[(size_t)ci*HW + px];
        const float4* wp = (const float4*)(s_w + ci*28);
        #pragma unroll
        for (int q=0;q<7;q++){
          float4 w4 = wp[q];
          acc[q*4+0] = fmaf(v, w4.x, acc[q*4+0]);
          acc[q*4+1] = fmaf(v, w4.y, acc[q*4+1]);
          acc[q*4+2] = fmaf(v, w4.z, acc[q*4+2]);
          acc[q*4+3] = fmaf(v, w4.w, acc[q*4+3]);
        }
      }
      #pragma unroll
      for (int j=0;j<27;j++) ob[(size_t)(cc*27+j)*HW + px] = acc[j];
    }
  }
}

// ---------------------------------------------------------------------------
// Per-pixel: softmax over 81 channels, argmax over first 80 (first-max wins),
// p = prob at argmax channel. (After masking only that channel is nonzero.)
// ---------------------------------------------------------------------------
__global__ void k_softmax(const float* __restrict__ logits){
  int i = blockIdx.x*256 + threadIdx.x;
  if (i >= BATCH*HW) return;
  int b = i / HW, px = i - b*HW;
  const float* lp = logits + (size_t)b*NC*HW + px;
  float M = -1e30f, best = -1e30f; int bi = 0;
  #pragma unroll 1
  for (int c=0;c<NC;c++){
    float v = lp[(size_t)c*HW];
    if (c < 80 && v > best){ best = v; bi = c; }
    M = fmaxf(M, v);
  }
  float s = 0.f;
  #pragma unroll 1
  for (int c=0;c<NC;c++) s += expf(lp[(size_t)c*HW] - M);
  g_pv[i] = expf(best - M) / s;
  g_cls[i] = bi;
}

// ---------------------------------------------------------------------------
// score = p + 1 if (p>=eps and no in-bounds 8-neighbor with same class and
// strictly larger p). Emits sortable key: (score_bits<<32) | (~px) so ties
// prefer the smaller index (lax.top_k semantics). score >= 0 always.
// ---------------------------------------------------------------------------
__global__ void k_score(){
  int i = blockIdx.x*256 + threadIdx.x;
  if (i >= BATCH*HW) return;
  int b = i / HW, px = i - b*HW;
  int y = px / WW, xx = px - y*WW;
  float p = g_pv[i]; int cls = g_cls[i];
  bool flag = (p >= 1e-6f);
  if (flag){
    #pragma unroll
    for (int dy=-1; dy<=1; dy++){
      #pragma unroll
      for (int dx=-1; dx<=1; dx++){
        if (dy==0 && dx==0) continue;
        int ny = y+dy, nx = xx+dx;
        if ((unsigned)ny < HH && (unsigned)nx < WW){
          int j = b*HW + ny*WW + nx;
          if (g_cls[j]==cls && g_pv[j] > p) flag = false;
        }
      }
    }
  }
  float score = p + (flag ? 1.f : 0.f);
  g_keys[i] = (((unsigned long long)__float_as_uint(score))<<32)
              | (unsigned long long)(0xFFFFFFFFu - (unsigned)px);
}

// ---------------------------------------------------------------------------
// Top-100 per batch: 100 iterations of block-wide argmax over 15200 keys
// (L2-resident), zero the winner each round. Exact lax.top_k ordering.
// ---------------------------------------------------------------------------
__global__ void k_topk(){
  __shared__ unsigned long long s_red[256];
  int b = blockIdx.x, tid = threadIdx.x;
  unsigned long long* kb = g_keys + (size_t)b*HW;
  for (int it=0; it<NKEEP; it++){
    unsigned long long best = 0ull;
    for (int i=tid; i<HW; i+=256){
      unsigned long long k = kb[i];
      if (k > best) best = k;
    }
    s_red[tid] = best;
    __syncthreads();
    #pragma unroll
    for (int s=128; s>0; s>>=1){
      if (tid < s && s_red[tid+s] > s_red[tid]) s_red[tid] = s_red[tid+s];
      __syncthreads();
    }
    unsigned long long win = s_red[0];
    int wpx = (int)(0xFFFFFFFFu - (unsigned)(win & 0xFFFFFFFFull));
    if (tid==0){
      g_topk[b*NKEEP+it] = wpx;
      kb[wpx] = 0ull;      // exclude winner; __syncthreads gives block visibility
    }
    __syncthreads();
  }
}

// ---------------------------------------------------------------------------
// Gather x and pos at top-k indices. out layout: [proposals | pos | logits]
// ---------------------------------------------------------------------------
__global__ void k_gather(const float* __restrict__ x, const float* __restrict__ pos,
                         float* __restrict__ out){
  int i = blockIdx.x*256 + threadIdx.x;
  if (i >= NOUT1) return;
  int k = i % NKEEP; int t = i / NKEEP; int c = t % CIN; int b = t / CIN;
  int px = g_topk[b*NKEEP + k];
  out[i]         = x[((size_t)b*CIN + c)*HW + px];
  out[NOUT1 + i] = pos[(size_t)c*HW + px];
}

// ---------------------------------------------------------------------------
extern "C" void kernel_launch(void* const* d_in, const int* in_sizes, int n_in,
                              void* d_out, int out_size){
  (void)in_sizes; (void)n_in; (void)out_size;
  const float* x   = (const float*)d_in[0];
  const float* pos = (const float*)d_in[1];
  const float* w1  = (const float*)d_in[2];
  const float* b1  = (const float*)d_in[3];
  const float* w2  = (const float*)d_in[4];
  const float* b2  = (const float*)d_in[5];
  float* out = (float*)d_out;
  float* logits = out + 2*NOUT1;

  k_transpose_w1<<<(CIN*CIN*9+255)/256, 256>>>(w1);
  k_conv3x3<<<dim3(10,7,BATCH*4), 256>>>(x, b1);
  k_conv1x1<<<dim3((HW+255)/256, BATCH), 256>>>(w2, b2, logits);
  k_softmax<<<(BATCH*HW+255)/256, 256>>>(logits);
  k_score<<<(BATCH*HW+255)/256, 256>>>();
  k_topk<<<BATCH, 256>>>();
  k_gather<<<(NOUT1+255)/256, 256>>>(x, pos, out);
}